// round 6
// baseline (speedup 1.0000x reference)
#include <cuda_runtime.h>
#include <math.h>

#define S_LEN 4096
#define BATCH 16
#define H2DIM 1024
#define NCHUNK 152
#define CHUNK ((S_LEN + NCHUNK - 1) / NCHUNK)   // 27
#define ROW_BYTES (BATCH * H2DIM * 4)           // 64KB per s-row
#define SLICE_BYTES (H2DIM * 4)                 // 4KB per (s,b) slice
#define NSTAGE 3
#define MBAR_OFF (NSTAGE * ROW_BYTES)
#define MAIN_SMEM (MBAR_OFF + 16 * NSTAGE * 8)
#define JC 4                                     // j-chunks in GEMV
#define JLEN (H2DIM / JC)                        // 256

// Scratch (allocation-free contract)
__device__ float g_part[JC][BATCH * H2DIM];      // GEMV partials per j-chunk
__device__ float g_wraw[BATCH * S_LEN];
__device__ float g_m[NCHUNK * BATCH];
__device__ float g_l[NCHUNK * BATCH];
__device__ float g_acc[(size_t)NCHUNK * BATCH * H2DIM];

// ---- packed f32x2 helpers ---------------------------------------------------
__device__ __forceinline__ unsigned long long fma2(unsigned long long a,
                                                   unsigned long long b,
                                                   unsigned long long c) {
    unsigned long long d;
    asm("fma.rn.f32x2 %0, %1, %2, %3;" : "=l"(d) : "l"(a), "l"(b), "l"(c));
    return d;
}
__device__ __forceinline__ unsigned long long mul2(unsigned long long a,
                                                   unsigned long long b) {
    unsigned long long d;
    asm("mul.rn.f32x2 %0, %1, %2;" : "=l"(d) : "l"(a), "l"(b));
    return d;
}
__device__ __forceinline__ unsigned long long pk2(float lo, float hi) {
    unsigned long long r;
    asm("mov.b64 %0, {%1, %2};" : "=l"(r) : "f"(lo), "f"(hi));
    return r;
}
__device__ __forceinline__ float2 upk2(unsigned long long v) {
    float2 r;
    asm("mov.b64 {%0, %1}, %2;" : "=f"(r.x), "=f"(r.y) : "l"(v));
    return r;
}
__device__ __forceinline__ float warp_sum(float v) {
#pragma unroll
    for (int off = 16; off > 0; off >>= 1)
        v += __shfl_xor_sync(0xffffffffu, v, off);
    return v;
}

// ---------------------------------------------------------------------------
// Kernel 1: GEMV partials. grid=(128,4), block=256 (8 warps).
// blockIdx.y = j-chunk (256 wide); block stages 16KB of state; each warp
// computes one row r for all 16 batches over its chunk. 512 blocks total.
// ---------------------------------------------------------------------------
__global__ void __launch_bounds__(256, 4)
k_altered(const float* __restrict__ state,
          const float* __restrict__ attn_w)
{
    __shared__ float4 s_st[BATCH * 64];           // [b][q<64] -> 16KB
    const int tid = threadIdx.x;
    const int wid = tid >> 5, lane = tid & 31;
    const int jc = blockIdx.y;
    const int r = blockIdx.x * 8 + wid;

    const float4* gs = (const float4*)state;
#pragma unroll
    for (int k = 0; k < 4; k++) {
        int idx = tid + 256 * k;                  // 0..1023
        int b = idx >> 6, q = idx & 63;
        s_st[idx] = __ldg(gs + b * 256 + jc * 64 + q);
    }
    __syncthreads();

    const float4* wr = (const float4*)(attn_w + (size_t)r * H2DIM + jc * JLEN);
    float4 wa = __ldg(wr + lane);
    float4 wb = __ldg(wr + lane + 32);
    ulonglong2 w0 = *(ulonglong2*)&wa;
    ulonglong2 w1 = *(ulonglong2*)&wb;

#pragma unroll 4
    for (int b = 0; b < BATCH; b++) {
        float4 sa = s_st[b * 64 + lane];
        float4 sb = s_st[b * 64 + lane + 32];
        ulonglong2 s0 = *(ulonglong2*)&sa;
        ulonglong2 s1 = *(ulonglong2*)&sb;
        unsigned long long a2 = 0ull;
        a2 = fma2(w0.x, s0.x, a2);
        a2 = fma2(w0.y, s0.y, a2);
        a2 = fma2(w1.x, s1.x, a2);
        a2 = fma2(w1.y, s1.y, a2);
        float2 f = upk2(a2);
        float tot = warp_sum(f.x + f.y);
        if (lane == 0)
            g_part[jc][b * H2DIM + r] = tot;
    }
}

// ---------------------------------------------------------------------------
// Kernel 2: single-pass online softmax, per-warp TMA bulk ring (3 slots).
// grid=152, block=512, warp b owns batch b. alt = sum of 4 GEMV partials + bias.
// ---------------------------------------------------------------------------
__global__ void __launch_bounds__(512, 1)
k_mainpass(const float* __restrict__ enc,
           const float* __restrict__ attn_b)
{
    extern __shared__ char smem[];
    const int tid = threadIdx.x;
    const int b = tid >> 5;
    const int lane = tid & 31;
    const int c = blockIdx.x;
    const int s0 = c * CHUNK;
    const int s1 = min(s0 + CHUNK, S_LEN);
    const int n = s1 - s0;

    const unsigned smem_u = (unsigned)__cvta_generic_to_shared(smem);
    const unsigned slice0 = smem_u + b * SLICE_BYTES;
    const unsigned mbar0 = smem_u + MBAR_OFF + b * (NSTAGE * 8);
    const char* gbase = (const char*)enc + (size_t)b * SLICE_BYTES;

    if (lane == 0) {
#pragma unroll
        for (int k = 0; k < NSTAGE; k++)
            asm volatile("mbarrier.init.shared.b64 [%0], 1;"
                         :: "r"(mbar0 + k * 8) : "memory");
        asm volatile("fence.proxy.async.shared::cta;" ::: "memory");
#pragma unroll
        for (int k = 0; k < NSTAGE; k++) {
            unsigned mb = mbar0 + k * 8;
            asm volatile("mbarrier.arrive.expect_tx.shared.b64 _, [%0], %1;"
                         :: "r"(mb), "r"(SLICE_BYTES) : "memory");
            asm volatile(
                "cp.async.bulk.shared::cluster.global.mbarrier::complete_tx::bytes "
                "[%0], [%1], %2, [%3];"
                :: "r"(slice0 + k * ROW_BYTES),
                   "l"(gbase + (size_t)(s0 + k) * ROW_BYTES),
                   "r"(SLICE_BYTES), "r"(mb) : "memory");
        }
    }

    // alt = g_part[0..3][b,:] + attn_b (overlaps with TMA prologue)
    unsigned long long alt2[16];
    {
        const float4* bias4 = (const float4*)attn_b;
#pragma unroll
        for (int k = 0; k < 8; k++) {
            int idx = lane + 32 * k;
            float4 v = __ldg(bias4 + idx);
#pragma unroll
            for (int jc = 0; jc < JC; jc++) {
                float4 pv = __ldg((const float4*)(g_part[jc] + b * H2DIM) + idx);
                v.x += pv.x; v.y += pv.y; v.z += pv.z; v.w += pv.w;
            }
            ulonglong2 t = *(ulonglong2*)&v;
            alt2[2 * k] = t.x;
            alt2[2 * k + 1] = t.y;
        }
    }

    unsigned long long acc2[16];
#pragma unroll
    for (int j = 0; j < 16; j++) acc2[j] = 0ull;
    float m = -1e30f, l = 0.f;

    int slot = 0, par = 0;
    for (int i = 0; i < n; i++) {
        const unsigned mb = mbar0 + slot * 8;
        unsigned done;
        asm volatile(
            "{\n\t.reg .pred p;\n\t"
            "mbarrier.try_wait.parity.acquire.cta.shared::cta.b64 p, [%1], %2;\n\t"
            "selp.b32 %0, 1, 0, p;\n\t}"
            : "=r"(done) : "r"(mb), "r"(par) : "memory");
        if (!done) {
            asm volatile(
                "{\n\t.reg .pred P1;\n\t"
                "W0_%=:\n\t"
                "mbarrier.try_wait.parity.acquire.cta.shared::cta.b64 P1, [%0], %1, 0x989680;\n\t"
                "@P1 bra.uni W1_%=;\n\t"
                "bra.uni W0_%=;\n\t"
                "W1_%=:\n\t}"
                :: "r"(mb), "r"(par) : "memory");
        }

        const ulonglong2* bp = (const ulonglong2*)(smem + slot * ROW_BYTES
                                                   + b * SLICE_BYTES);
        ulonglong2 e2[8];
#pragma unroll
        for (int k = 0; k < 8; k++) e2[k] = bp[lane + 32 * k];

        // slot drained -> re-issue immediately (lane 0)
        int nxt = i + NSTAGE;
        if (nxt < n && lane == 0) {
            asm volatile("mbarrier.arrive.expect_tx.shared.b64 _, [%0], %1;"
                         :: "r"(mb), "r"(SLICE_BYTES) : "memory");
            asm volatile(
                "cp.async.bulk.shared::cluster.global.mbarrier::complete_tx::bytes "
                "[%0], [%1], %2, [%3];"
                :: "r"(slice0 + slot * ROW_BYTES),
                   "l"(gbase + (size_t)(s0 + nxt) * ROW_BYTES),
                   "r"(SLICE_BYTES), "r"(mb) : "memory");
        }

        unsigned long long w2 = 0ull;
#pragma unroll
        for (int k = 0; k < 8; k++) {
            w2 = fma2(e2[k].x, alt2[2 * k], w2);
            w2 = fma2(e2[k].y, alt2[2 * k + 1], w2);
        }
        float2 wp = upk2(w2);
        float w = warp_sum(wp.x + wp.y);

        if (w > m) {                               // warp-uniform
            float sc = __expf(m - w);
            m = w;
            l *= sc;
            unsigned long long sc2 = pk2(sc, sc);
#pragma unroll
            for (int j = 0; j < 16; j++) acc2[j] = mul2(acc2[j], sc2);
        }
        float p = __expf(w - m);
        l += p;
        unsigned long long p2 = pk2(p, p);
#pragma unroll
        for (int k = 0; k < 8; k++) {
            acc2[2 * k]     = fma2(p2, e2[k].x, acc2[2 * k]);
            acc2[2 * k + 1] = fma2(p2, e2[k].y, acc2[2 * k + 1]);
        }
        if (lane == 0) g_wraw[b * S_LEN + s0 + i] = w;

        if (++slot == NSTAGE) { slot = 0; par ^= 1; }
    }

    if (lane == 0) {
        g_m[c * BATCH + b] = m;
        g_l[c * BATCH + b] = l;
    }
    float4* outp = (float4*)(g_acc + ((size_t)c * BATCH + b) * H2DIM);
#pragma unroll
    for (int k = 0; k < 8; k++) {
        float2 a = upk2(acc2[2 * k]);
        float2 bq = upk2(acc2[2 * k + 1]);
        outp[lane + 32 * k] = make_float4(a.x, a.y, bq.x, bq.y);
    }
}

// ---------------------------------------------------------------------------
// Kernel 3: finish. grid = (BATCH, 24), block 512.
// t in [0,16): attention_applied d-tile of 64, 8 parallel c2-groups.
// t in [16,24): normalized_weights s-tile of 512.
// ---------------------------------------------------------------------------
__global__ void __launch_bounds__(512, 2)
k_finish(float* __restrict__ out)
{
    const int b = blockIdx.x;
    const int t = blockIdx.y;
    const int tid = threadIdx.x;
    __shared__ float sM, sInvL;
    __shared__ float s_coef[NCHUNK];
    __shared__ float s_part[512];

    if (tid < 32) {
        float mx = -1e30f;
        for (int c2 = tid; c2 < NCHUNK; c2 += 32)
            mx = fmaxf(mx, g_m[c2 * BATCH + b]);
#pragma unroll
        for (int off = 16; off > 0; off >>= 1)
            mx = fmaxf(mx, __shfl_xor_sync(0xffffffffu, mx, off));
        float ls = 0.f;
        for (int c2 = tid; c2 < NCHUNK; c2 += 32)
            ls += __expf(g_m[c2 * BATCH + b] - mx) * g_l[c2 * BATCH + b];
        ls = warp_sum(ls);
        if (tid == 0) { sM = mx; sInvL = 1.f / ls; }
    }
    __syncthreads();
    const float M = sM, invL = sInvL;

    if (t < 16) {
        if (tid < NCHUNK) s_coef[tid] = __expf(g_m[tid * BATCH + b] - M);
        __syncthreads();
        const int doff = tid & 63;
        const int g = tid >> 6;                 // 0..7
        const int d = t * 64 + doff;
        float a = 0.f;
#pragma unroll
        for (int k = 0; k < 19; k++) {          // 152 = 8 * 19
            int c2 = g + 8 * k;
            a = fmaf(s_coef[c2], g_acc[((size_t)c2 * BATCH + b) * H2DIM + d], a);
        }
        s_part[tid] = a;
        __syncthreads();
        if (tid < 64) {
            float v = 0.f;
#pragma unroll
            for (int gg = 0; gg < 8; gg++) v += s_part[gg * 64 + tid];
            out[b * H2DIM + d] = v * invL;
        }
    } else {
        const int s = (t - 16) * 512 + tid;
        out[BATCH * H2DIM + b * S_LEN + s] =
            __expf(g_wraw[b * S_LEN + s] - M) * invL;
    }
}

// ---------------------------------------------------------------------------
extern "C" void kernel_launch(void* const* d_in, const int* in_sizes, int n_in,
                              void* d_out, int out_size)
{
    const float* enc    = (const float*)d_in[0];
    const float* state  = (const float*)d_in[1];
    const float* attn_w = (const float*)d_in[3];
    const float* attn_b = (const float*)d_in[4];
    float* out = (float*)d_out;

    cudaFuncSetAttribute(k_mainpass,
        cudaFuncAttributeMaxDynamicSharedMemorySize, MAIN_SMEM);

    k_altered<<<dim3(128, JC), 256>>>(state, attn_w);
    k_mainpass<<<NCHUNK, 512, MAIN_SMEM>>>(enc, attn_b);
    k_finish<<<dim3(BATCH, 24), 512>>>(out);
}

// round 7
// speedup vs baseline: 1.0083x; 1.0083x over previous
#include <cuda_runtime.h>
#include <math.h>

#define S_LEN 4096
#define BATCH 16
#define H2DIM 1024
#define NBLK 148
#define CHUNK 28                                  // ceil(4096/148)
#define ROW_BYTES (BATCH * H2DIM * 4)             // 64KB per s-row
#define SLICE_BYTES (H2DIM * 4)                   // 4KB per (s,b) slice
#define NSTAGE 3
#define MBAR_OFF (NSTAGE * ROW_BYTES)
#define MAIN_SMEM (MBAR_OFF + 16 * NSTAGE * 8)
#define STATE_SMEM_OFF (2 * ROW_BYTES)            // state staged over slot 2

// Scratch (allocation-free contract)
__device__ float g_alt[BATCH * H2DIM];            // altered_state (+bias)
__device__ float g_wraw[BATCH * S_LEN];
__device__ float g_m[NBLK * BATCH];
__device__ float g_l[NBLK * BATCH];
__device__ float g_acc[(size_t)NBLK * BATCH * H2DIM];
__device__ unsigned g_bar;                        // up/down grid barrier (self-cleaning)

// ---- packed f32x2 helpers ----------------------------------------------------
__device__ __forceinline__ unsigned long long fma2(unsigned long long a,
                                                   unsigned long long b,
                                                   unsigned long long c) {
    unsigned long long d;
    asm("fma.rn.f32x2 %0, %1, %2, %3;" : "=l"(d) : "l"(a), "l"(b), "l"(c));
    return d;
}
__device__ __forceinline__ unsigned long long mul2(unsigned long long a,
                                                   unsigned long long b) {
    unsigned long long d;
    asm("mul.rn.f32x2 %0, %1, %2;" : "=l"(d) : "l"(a), "l"(b));
    return d;
}
__device__ __forceinline__ unsigned long long pk2(float lo, float hi) {
    unsigned long long r;
    asm("mov.b64 %0, {%1, %2};" : "=l"(r) : "f"(lo), "f"(hi));
    return r;
}
__device__ __forceinline__ float2 upk2(unsigned long long v) {
    float2 r;
    asm("mov.b64 {%0, %1}, %2;" : "=f"(r.x), "=f"(r.y) : "l"(v));
    return r;
}
__device__ __forceinline__ float warp_sum(float v) {
#pragma unroll
    for (int off = 16; off > 0; off >>= 1)
        v += __shfl_xor_sync(0xffffffffu, v, off);
    return v;
}

// up barrier: inc, wait until count >= NBLK
__device__ __forceinline__ void bar_up() {
    __syncthreads();
    if (threadIdx.x == 0) {
        __threadfence();
        atomicAdd(&g_bar, 1u);
        volatile unsigned* p = &g_bar;
        while (*p < NBLK) __nanosleep(64);
        __threadfence();
    }
    __syncthreads();
}
// down barrier: dec, wait until count == 0 (leaves counter 0 for next replay)
__device__ __forceinline__ void bar_down() {
    __syncthreads();
    if (threadIdx.x == 0) {
        __threadfence();
        atomicSub(&g_bar, 1u);
        volatile unsigned* p = &g_bar;
        while (*p != 0u) __nanosleep(64);
        __threadfence();
    }
    __syncthreads();
}

__device__ __forceinline__ void tma_slice(unsigned sdst, const char* gsrc, unsigned mb) {
    asm volatile("mbarrier.arrive.expect_tx.shared.b64 _, [%0], %1;"
                 :: "r"(mb), "r"(SLICE_BYTES) : "memory");
    asm volatile(
        "cp.async.bulk.shared::cluster.global.mbarrier::complete_tx::bytes "
        "[%0], [%1], %2, [%3];"
        :: "r"(sdst), "l"(gsrc), "r"(SLICE_BYTES), "r"(mb) : "memory");
}

// ---------------------------------------------------------------------------
// Fused persistent kernel. grid = 148, block = 512, 1 CTA/SM.
// ---------------------------------------------------------------------------
__global__ void __launch_bounds__(512, 1)
k_fused(const float* __restrict__ enc,
        const float* __restrict__ state,
        const float* __restrict__ attn_w,
        const float* __restrict__ attn_b,
        float* __restrict__ out)
{
    extern __shared__ char smem[];
    const int tid = threadIdx.x;
    const int b = tid >> 5;
    const int lane = tid & 31;
    const int c = blockIdx.x;
    const int s0 = c * CHUNK;
    const int s1 = min(s0 + CHUNK, S_LEN);
    const int n = max(s1 - s0, 0);

    const unsigned smem_u = (unsigned)__cvta_generic_to_shared(smem);
    const unsigned slice0 = smem_u + b * SLICE_BYTES;
    const unsigned mbar0 = smem_u + MBAR_OFF + b * (NSTAGE * 8);
    const char* gbase = (const char*)enc + (size_t)b * SLICE_BYTES;

    // ---- init mbars + issue slots 0,1 (overlaps phase A GEMV) ----
    if (lane == 0) {
#pragma unroll
        for (int k = 0; k < NSTAGE; k++)
            asm volatile("mbarrier.init.shared.b64 [%0], 1;"
                         :: "r"(mbar0 + k * 8) : "memory");
        asm volatile("fence.proxy.async.shared::cta;" ::: "memory");
#pragma unroll
        for (int k = 0; k < 2; k++)
            if (k < n)
                tma_slice(slice0 + k * ROW_BYTES,
                          gbase + (size_t)(s0 + k) * ROW_BYTES, mbar0 + k * 8);
    }

    // ---- Phase A: GEMV (blocks 0..127, 8 rows each) ----
    if (c < 128) {
        float4* sst = (float4*)(smem + STATE_SMEM_OFF);        // 64KB state
        const float4* gs = (const float4*)state;
#pragma unroll
        for (int k = 0; k < 8; k++)
            sst[tid + 512 * k] = __ldg(gs + tid + 512 * k);
        __syncthreads();

        const int r = c * 8 + (b >> 1);                        // b==wid here
        const int bg = (b & 1) * 8;
        const float4* wr = (const float4*)(attn_w + (size_t)r * H2DIM);
        ulonglong2 wv[8];
#pragma unroll
        for (int k = 0; k < 8; k++) {
            float4 v = __ldg(wr + lane + 32 * k);
            wv[k] = *(ulonglong2*)&v;
        }
        const float bias = __ldg(attn_b + r);
#pragma unroll 2
        for (int bb = 0; bb < 8; bb++) {
            const float4* sp = sst + (bg + bb) * (H2DIM / 4);
            unsigned long long a2 = 0ull;
#pragma unroll
            for (int k = 0; k < 8; k++) {
                float4 s = sp[lane + 32 * k];
                ulonglong2 s2 = *(ulonglong2*)&s;
                a2 = fma2(wv[k].x, s2.x, a2);
                a2 = fma2(wv[k].y, s2.y, a2);
            }
            float2 f = upk2(a2);
            float tot = warp_sum(f.x + f.y);
            if (lane == 0)
                g_alt[(bg + bb) * H2DIM + r] = tot + bias;
        }
    }

    // ---- barrier 1: g_alt ready everywhere ----
    bar_up();

    // ---- load alt, issue slot 2 ----
    unsigned long long alt2[16];
    {
        const float4* ap = (const float4*)(g_alt + b * H2DIM);
#pragma unroll
        for (int k = 0; k < 8; k++) {
            float4 v = __ldg(ap + lane + 32 * k);
            ulonglong2 t = *(ulonglong2*)&v;
            alt2[2 * k] = t.x;
            alt2[2 * k + 1] = t.y;
        }
    }
    if (lane == 0 && 2 < n)
        tma_slice(slice0 + 2 * ROW_BYTES,
                  gbase + (size_t)(s0 + 2) * ROW_BYTES, mbar0 + 2 * 8);

    // ---- Phase B: online-softmax mainloop (per-warp TMA ring) ----
    unsigned long long acc2[16];
#pragma unroll
    for (int j = 0; j < 16; j++) acc2[j] = 0ull;
    float m = -1e30f, l = 0.f;

    int slot = 0, par = 0;
    for (int i = 0; i < n; i++) {
        const unsigned mb = mbar0 + slot * 8;
        unsigned done;
        asm volatile(
            "{\n\t.reg .pred p;\n\t"
            "mbarrier.try_wait.parity.acquire.cta.shared::cta.b64 p, [%1], %2;\n\t"
            "selp.b32 %0, 1, 0, p;\n\t}"
            : "=r"(done) : "r"(mb), "r"(par) : "memory");
        if (!done) {
            asm volatile(
                "{\n\t.reg .pred P1;\n\t"
                "W0_%=:\n\t"
                "mbarrier.try_wait.parity.acquire.cta.shared::cta.b64 P1, [%0], %1, 0x989680;\n\t"
                "@P1 bra.uni W1_%=;\n\t"
                "bra.uni W0_%=;\n\t"
                "W1_%=:\n\t}"
                :: "r"(mb), "r"(par) : "memory");
        }

        const ulonglong2* bp = (const ulonglong2*)(smem + slot * ROW_BYTES
                                                   + b * SLICE_BYTES);
        ulonglong2 e2[8];
#pragma unroll
        for (int k = 0; k < 8; k++) e2[k] = bp[lane + 32 * k];

        int nxt = i + NSTAGE;
        if (nxt < n && lane == 0)
            tma_slice(slice0 + slot * ROW_BYTES,
                      gbase + (size_t)(s0 + nxt) * ROW_BYTES, mb);

        unsigned long long w2 = 0ull;
#pragma unroll
        for (int k = 0; k < 8; k++) {
            w2 = fma2(e2[k].x, alt2[2 * k], w2);
            w2 = fma2(e2[k].y, alt2[2 * k + 1], w2);
        }
        float2 wp = upk2(w2);
        float w = warp_sum(wp.x + wp.y);

        if (w > m) {                                   // warp-uniform
            float sc = __expf(m - w);
            m = w;
            l *= sc;
            unsigned long long sc2 = pk2(sc, sc);
#pragma unroll
            for (int j = 0; j < 16; j++) acc2[j] = mul2(acc2[j], sc2);
        }
        float p = __expf(w - m);
        l += p;
        unsigned long long p2 = pk2(p, p);
#pragma unroll
        for (int k = 0; k < 8; k++) {
            acc2[2 * k]     = fma2(p2, e2[k].x, acc2[2 * k]);
            acc2[2 * k + 1] = fma2(p2, e2[k].y, acc2[2 * k + 1]);
        }
        if (lane == 0) g_wraw[b * S_LEN + s0 + i] = w;

        if (++slot == NSTAGE) { slot = 0; par ^= 1; }
    }

    if (lane == 0) {
        g_m[c * BATCH + b] = m;
        g_l[c * BATCH + b] = l;
    }
    float4* outp = (float4*)(g_acc + ((size_t)c * BATCH + b) * H2DIM);
#pragma unroll
    for (int k = 0; k < 8; k++) {
        float2 a = upk2(acc2[2 * k]);
        float2 bq = upk2(acc2[2 * k + 1]);
        outp[lane + 32 * k] = make_float4(a.x, a.y, bq.x, bq.y);
    }

    // ---- barrier 2: all partials ready ----
    bar_down();

    // ---- Phase C: finish. 256 tiles over 148 blocks ----
    float* sfin = (float*)smem;                     // reuse slot area
    float* s_coef = sfin;                           // [148]
    float* s_part = sfin + 160;                     // [512]
    float* s_ml   = sfin + 160 + 512;               // M, invL

#pragma unroll 1
    for (int pass = 0; pass < 2; pass++) {
        int T = (pass == 0) ? c : c + NBLK;
        if (T >= 256) break;
        const int isApplied = (T < 128);
        const int W = isApplied ? T : T - 128;
        const int bb = W >> 3;

        if (tid < 32) {                              // per-tile M, L
            float mx = -1e30f;
            for (int c2 = tid; c2 < NBLK; c2 += 32)
                mx = fmaxf(mx, g_m[c2 * BATCH + bb]);
#pragma unroll
            for (int off = 16; off > 0; off >>= 1)
                mx = fmaxf(mx, __shfl_xor_sync(0xffffffffu, mx, off));
            float ls = 0.f;
            for (int c2 = tid; c2 < NBLK; c2 += 32)
                ls += __expf(g_m[c2 * BATCH + bb] - mx) * g_l[c2 * BATCH + bb];
            ls = warp_sum(ls);
            if (tid == 0) { s_ml[0] = mx; s_ml[1] = 1.f / ls; }
        }
        __syncthreads();
        const float M = s_ml[0], invL = s_ml[1];

        if (isApplied) {
            if (tid < NBLK) s_coef[tid] = __expf(g_m[tid * BATCH + bb] - M);
            __syncthreads();
            const int g = tid >> 7;                  // 0..3
            const int doff = tid & 127;
            const int d = (W & 7) * 128 + doff;
            float a = 0.f;
#pragma unroll
            for (int k = 0; k < 37; k++) {           // 148 = 4 * 37
                int c2 = g + 4 * k;
                a = fmaf(s_coef[c2],
                         g_acc[((size_t)c2 * BATCH + bb) * H2DIM + d], a);
            }
            s_part[tid] = a;
            __syncthreads();
            if (tid < 128) {
                float v = s_part[tid] + s_part[128 + tid]
                        + s_part[256 + tid] + s_part[384 + tid];
                out[bb * H2DIM + d] = v * invL;
            }
            __syncthreads();
        } else {
            const int s = (W & 7) * 512 + tid;
            out[BATCH * H2DIM + bb * S_LEN + s] =
                __expf(g_wraw[bb * S_LEN + s] - M) * invL;
            __syncthreads();
        }
    }
}

// ---------------------------------------------------------------------------
extern "C" void kernel_launch(void* const* d_in, const int* in_sizes, int n_in,
                              void* d_out, int out_size)
{
    const float* enc    = (const float*)d_in[0];
    const float* state  = (const float*)d_in[1];
    const float* attn_w = (const float*)d_in[3];
    const float* attn_b = (const float*)d_in[4];
    float* out = (float*)d_out;

    cudaFuncSetAttribute(k_fused,
        cudaFuncAttributeMaxDynamicSharedMemorySize, MAIN_SMEM);

    k_fused<<<NBLK, 512, MAIN_SMEM>>>(enc, state, attn_w, attn_b, out);
}